// round 17
// baseline (speedup 1.0000x reference)
#include <cuda_runtime.h>
#include <cuda_bf16.h>
#include <cuda_fp16.h>
#include <cstdint>

// Problem constants
#define S_LEN 1025
#define B_SZ  8
#define E_SZ  1024
#define H_CNT 16
#define HD    64
#define NTOK  (S_LEN * B_SZ)          // 8200
#define NTOK_PROJ (1024 * B_SZ)       // 8192
#define QSCALE 0.180336880f           // 0.125 * log2(e)

// ---------------- scratch (device globals: allocation-free) ----------------
__device__ __half g_qraw[NTOK_PROJ * E_SZ];
__device__ __half g_kraw[NTOK_PROJ * E_SZ];
__device__ __half g_vraw[NTOK_PROJ * E_SZ];
__device__ __half g_wi[3072 * 1024];
__device__ __half g_wo[1024 * 1024];
__device__ __half g_aq[NTOK * E_SZ];      // projected q (pre-scaled by 0.125*log2e)
__device__ __half g_ak[NTOK * E_SZ];
__device__ __half g_av[NTOK * E_SZ];
__device__ __half g_c[NTOK * E_SZ];       // ctx, single fp16

// ---------------- helpers ----------------
__device__ __forceinline__ uint32_t smem_u32(const void* p) {
    uint32_t a;
    asm("{ .reg .u64 t; cvta.to.shared.u64 t, %1; cvt.u32.u64 %0, t; }"
        : "=r"(a) : "l"(p));
    return a;
}
__device__ __forceinline__ void ldsm4(uint32_t* r, uint32_t addr) {
    asm volatile("ldmatrix.sync.aligned.m8n8.x4.shared.b16 {%0,%1,%2,%3}, [%4];"
                 : "=r"(r[0]), "=r"(r[1]), "=r"(r[2]), "=r"(r[3]) : "r"(addr));
}
__device__ __forceinline__ void ldsm4_t(uint32_t* r, uint32_t addr) {
    asm volatile("ldmatrix.sync.aligned.m8n8.x4.trans.shared.b16 {%0,%1,%2,%3}, [%4];"
                 : "=r"(r[0]), "=r"(r[1]), "=r"(r[2]), "=r"(r[3]) : "r"(addr));
}
__device__ __forceinline__ void mma_f16(float* d, const uint32_t* a, const uint32_t* b) {
    asm volatile(
        "mma.sync.aligned.m16n8k16.row.col.f32.f16.f16.f32 "
        "{%0,%1,%2,%3}, {%4,%5,%6,%7}, {%8,%9}, {%0,%1,%2,%3};"
        : "+f"(d[0]), "+f"(d[1]), "+f"(d[2]), "+f"(d[3])
        : "r"(a[0]), "r"(a[1]), "r"(a[2]), "r"(a[3]), "r"(b[0]), "r"(b[1]));
}
__device__ __forceinline__ float ex2f(float x) {
    float r;
    asm("ex2.approx.ftz.f32 %0, %1;" : "=f"(r) : "f"(x));
    return r;
}
#define CP_ASYNC16(dst, src, sz) \
    asm volatile("cp.async.cg.shared.global [%0], [%1], 16, %2;" \
                 :: "r"(dst), "l"(src), "r"(sz))
#define CP_COMMIT() asm volatile("cp.async.commit_group;" ::: "memory")
#define CP_WAIT(n)  asm volatile("cp.async.wait_group %0;" :: "n"(n) : "memory")

__device__ __forceinline__ uint32_t pack2h(float a, float b) {
    __half2 h = __floats2half2_rn(a, b);
    return *(uint32_t*)&h;
}

// ---------------------------------------------------------------------------
// 1-term fp16 GEMM v2: 128x128 CTA tile, BK=64, 4 warps (2x2, m64xn64 each),
// 128 threads, 3-stage cp.async. Fragment dup: A 2x, W 2x (was 4x/2x).
// ---------------------------------------------------------------------------
#define OP_BYTES    (128 * 128)
#define STAGE_BYTES (2 * OP_BYTES)        // 32 KB
#define GK_SMEM     (3 * STAGE_BYTES)     // 96 KB

__device__ __forceinline__ void load_stage(
    char* stage, const __half* __restrict__ A, const __half* __restrict__ W,
    int m0, int n0, int k0, int M, int tid)
{
#pragma unroll
    for (int o = 0; o < 2; ++o) {
        const __half* src_base = (o == 0) ? A : W;
        const int row0 = (o == 0) ? m0 : n0;
        char* dstop = stage + o * OP_BYTES;
#pragma unroll
        for (int i = 0; i < 8; ++i) {
            int ch = i * 128 + tid;          // 1024 chunks over 128 threads
            int r = ch >> 3, c = ch & 7;
            uint32_t dst = smem_u32(dstop + r * 128 + ((c ^ (r & 7)) << 4));
            const char* src = (const char*)(src_base + (size_t)(row0 + r) * 1024 + k0 + c * 8);
            int sz = (o == 1 || (row0 + r) < M) ? 16 : 0;
            CP_ASYNC16(dst, src, sz);
        }
    }
}

template<int OUT_MODE>   // 0: fp32 C; 2: fp16 H * oscale
__device__ __forceinline__ void tc_gemm_body(
    const __half* __restrict__ A, const __half* __restrict__ W,
    const float* __restrict__ bias, float* __restrict__ C,
    __half* __restrict__ H, float oscale, int M,
    char* sm, int n0, int m0)
{
    const int tid = threadIdx.x;
    const int wid = tid >> 5, lane = tid & 31;
    const int wm = wid >> 1, wn = wid & 1;       // 2 x 2 warp grid, m64 x n64 tiles

    float acc[4][8][4];                           // [mt][n8 tile][frag]
#pragma unroll
    for (int a = 0; a < 4; ++a)
#pragma unroll
        for (int b = 0; b < 8; ++b)
#pragma unroll
            for (int c = 0; c < 4; ++c) acc[a][b][c] = 0.f;

    const int a_row_l = lane & 15;
    const int a_chk_l = lane >> 4;
    const int b_row_l = (lane & 7) + ((lane >> 4) << 3);
    const int b_chk_l = (lane >> 3) & 1;

    load_stage(sm,               A, W, m0, n0, 0,  M, tid); CP_COMMIT();
    load_stage(sm + STAGE_BYTES, A, W, m0, n0, 64, M, tid); CP_COMMIT();

    int cur = 0, pre = 2;
    for (int t = 0; t < 16; ++t) {
        CP_WAIT(1);
        __syncthreads();
        if (t + 2 < 16)
            load_stage(sm + pre * STAGE_BYTES, A, W, m0, n0, (t + 2) * 64, M, tid);
        CP_COMMIT();

        char* st = sm + cur * STAGE_BYTES;
        const uint32_t sA = smem_u32(st);
        const uint32_t sW = sA + OP_BYTES;

#pragma unroll
        for (int ks = 0; ks < 4; ++ks) {
            uint32_t a4[4][4], w[4][4];
            const int achk = ks * 2 + a_chk_l;
#pragma unroll
            for (int mt = 0; mt < 4; ++mt) {
                int row = wm * 64 + mt * 16 + a_row_l;
                ldsm4(a4[mt], sA + row * 128 + ((achk ^ (row & 7)) << 4));
            }
            const int bchk = ks * 2 + b_chk_l;
#pragma unroll
            for (int np = 0; np < 4; ++np) {
                int row = wn * 64 + np * 16 + b_row_l;
                ldsm4(w[np], sW + row * 128 + ((bchk ^ (row & 7)) << 4));
            }
#pragma unroll
            for (int mt = 0; mt < 4; ++mt)
#pragma unroll
                for (int np = 0; np < 4; ++np) {
                    mma_f16(acc[mt][np * 2],     a4[mt], &w[np][0]);
                    mma_f16(acc[mt][np * 2 + 1], a4[mt], &w[np][2]);
                }
        }
        cur = (cur == 2) ? 0 : cur + 1;
        pre = (pre == 2) ? 0 : pre + 1;
    }

#pragma unroll
    for (int mt = 0; mt < 4; ++mt) {
        int mA = m0 + wm * 64 + mt * 16 + (lane >> 2);
        int mB = mA + 8;
#pragma unroll
        for (int nt = 0; nt < 8; ++nt) {
            int n = n0 + wn * 64 + nt * 8 + (lane & 3) * 2;
            float2 bv = *(const float2*)&bias[n];
            float v0 = acc[mt][nt][0] + bv.x, v1 = acc[mt][nt][1] + bv.y;
            float v2 = acc[mt][nt][2] + bv.x, v3 = acc[mt][nt][3] + bv.y;
            if (OUT_MODE == 2) {
                if (mA < M) {
                    __half2 hv = __floats2half2_rn(v0 * oscale, v1 * oscale);
                    *(uint32_t*)(H + (size_t)mA * 1024 + n) = *(uint32_t*)&hv;
                }
                if (mB < M) {
                    __half2 hv = __floats2half2_rn(v2 * oscale, v3 * oscale);
                    *(uint32_t*)(H + (size_t)mB * 1024 + n) = *(uint32_t*)&hv;
                }
            } else {
                if (mA < M) *(float2*)&C[(size_t)mA * 1024 + n] = make_float2(v0, v1);
                if (mB < M) *(float2*)&C[(size_t)mB * 1024 + n] = make_float2(v2, v3);
            }
        }
    }
}

__global__ __launch_bounds__(128)
void tc_gemm_qkv(const __half* __restrict__ qraw, const __half* __restrict__ kraw,
                 const __half* __restrict__ vraw,
                 const __half* __restrict__ W, const float* __restrict__ bias,
                 __half* __restrict__ oq, __half* __restrict__ ok, __half* __restrict__ ov)
{
    extern __shared__ char sm[];
    const int z = blockIdx.z;
    const __half* A = (z == 0) ? qraw : (z == 1) ? kraw : vraw;
    __half* H = (z == 0) ? oq : (z == 1) ? ok : ov;
    tc_gemm_body<2>(A, W + (size_t)z * 1024 * 1024, bias + z * 1024,
                    nullptr, H, (z == 0) ? QSCALE : 1.f, NTOK_PROJ, sm,
                    blockIdx.x * 128, blockIdx.y * 128);
}

__global__ __launch_bounds__(128)
void tc_gemm_out(const __half* __restrict__ A, const __half* __restrict__ W,
                 const float* __restrict__ bias, float* __restrict__ C, int M)
{
    extern __shared__ char sm[];
    tc_gemm_body<0>(A, W, bias, C, nullptr, 1.f, M, sm,
                    blockIdx.x * 128, blockIdx.y * 128);
}

// ---------------------------------------------------------------------------
// Fused input conversion (4 elems/thread) + dummy-row fill at tail
// ---------------------------------------------------------------------------
#define NQ4  (NTOK_PROJ * E_SZ / 4)          // 2,097,152
#define NWI4 (3072 * 1024 / 4)
#define NWO4 (1024 * 1024 / 4)
#define NSPLIT_TOT (3 * NQ4 + NWI4 + NWO4)   // 7,340,032
#define FILL4 2048
#define SPLIT_EXT (NSPLIT_TOT + FILL4)

__global__ __launch_bounds__(256) void split_all(
    const float4* __restrict__ q, const float4* __restrict__ k, const float4* __restrict__ v,
    const float4* __restrict__ wi, const float4* __restrict__ wo,
    uint2* __restrict__ qo, uint2* __restrict__ ko, uint2* __restrict__ vo,
    uint2* __restrict__ wih, uint2* __restrict__ woh,
    uint2* __restrict__ aq2, uint2* __restrict__ ak2, uint2* __restrict__ av2)
{
    int base = blockIdx.x * 1024 + threadIdx.x;
#pragma unroll
    for (int u = 0; u < 4; ++u) {
        int i = base + u * 256;
        if (i >= SPLIT_EXT) break;
        if (i >= NSPLIT_TOT) {
            int off = i - NSPLIT_TOT;
            float4 val = q[NQ4 + off];       // query row 1024
            uint2 hk;
            __half2 k01 = __floats2half2_rn(val.x, val.y);
            __half2 k23 = __floats2half2_rn(val.z, val.w);
            hk.x = *(uint32_t*)&k01; hk.y = *(uint32_t*)&k23;
            uint2 hq;
            __half2 q01 = __floats2half2_rn(val.x * QSCALE, val.y * QSCALE);
            __half2 q23 = __floats2half2_rn(val.z * QSCALE, val.w * QSCALE);
            hq.x = *(uint32_t*)&q01; hq.y = *(uint32_t*)&q23;
            aq2[NQ4 + off] = hq;
            ak2[NQ4 + off] = hk;
            av2[NQ4 + off] = hk;
            continue;
        }
        const float4* src; uint2* dst; int off;
        if (i < NQ4)                 { src = q;  dst = qo;  off = i; }
        else if (i < 2 * NQ4)        { src = k;  dst = ko;  off = i - NQ4; }
        else if (i < 3 * NQ4)        { src = v;  dst = vo;  off = i - 2 * NQ4; }
        else if (i < 3 * NQ4 + NWI4) { src = wi; dst = wih; off = i - 3 * NQ4; }
        else                         { src = wo; dst = woh; off = i - 3 * NQ4 - NWI4; }
        float4 val = src[off];
        __half2 h01 = __floats2half2_rn(val.x, val.y);
        __half2 h23 = __floats2half2_rn(val.z, val.w);
        dst[off] = make_uint2(*(uint32_t*)&h01, *(uint32_t*)&h23);
    }
}

// ---------------------------------------------------------------------------
// Flash attention (unchanged from R16): fp16 mma.sync, 4 warps x m32
// ---------------------------------------------------------------------------
#define ATTN_SMEM (16384 + 2 * 16384)

__global__ __launch_bounds__(128) void attn_f16(
    const __half* __restrict__ Qf, const __half* __restrict__ Kf,
    const __half* __restrict__ Vf, __half* __restrict__ Ctx)
{
    extern __shared__ char sm[];
    const int tid = threadIdx.x, wid = tid >> 5, lane = tid & 31;
    const int qt = blockIdx.x;
    const int b = blockIdx.y >> 4, h = blockIdx.y & 15;
    const size_t colb = (size_t)h * 64;

#pragma unroll
    for (int i = 0; i < 8; ++i) {
        int ch = i * 128 + tid;
        int r = ch >> 3, c = ch & 7;
        uint32_t dst = smem_u32(sm + r * 128 + ((c ^ (r & 7)) << 4));
        int tok = qt * 128 + r;
        const char* src = (const char*)(Qf + (size_t)(tok * 8 + b) * 1024 + colb + c * 8);
        CP_ASYNC16(dst, src, tok <= 1024 ? 16 : 0);
    }

    auto load_kv = [&](int kb, int st) {
        char* sbase = sm + 16384 + st * 16384;
#pragma unroll
        for (int i = 0; i < 8; ++i) {
            int ch = i * 128 + tid;
            int arr = ch >> 9, cc = ch & 511;
            int r = cc >> 3, c = cc & 7;
            uint32_t dst = smem_u32(sbase + arr * 8192 + r * 128 + ((c ^ (r & 7)) << 4));
            int tok = kb * 64 + r;
            const __half* p = arr ? Vf : Kf;
            const char* src = (const char*)(p + (size_t)(tok * 8 + b) * 1024 + colb + c * 8);
            CP_ASYNC16(dst, src, tok <= 1024 ? 16 : 0);
        }
    };
    load_kv(0, 0);
    CP_COMMIT();

    float o[2][8][4];
#pragma unroll
    for (int mt = 0; mt < 2; ++mt)
#pragma unroll
        for (int nt = 0; nt < 8; ++nt)
#pragma unroll
            for (int j = 0; j < 4; ++j) o[mt][nt][j] = 0.f;
    float mr[2][2], lr[2][2];
#pragma unroll
    for (int mt = 0; mt < 2; ++mt) {
        mr[mt][0] = -1e30f; mr[mt][1] = -1e30f;
        lr[mt][0] = 0.f;    lr[mt][1] = 0.f;
    }

    const int a_row_l = lane & 15;
    const int a_chk_l = lane >> 4;
    const int b_row_l = (lane & 7) + ((lane >> 4) << 3);
    const int b_chk_l = (lane >> 3) & 1;
    const uint32_t sQb = smem_u32(sm);

    for (int kb = 0; kb < 17; ++kb) {
        if (kb + 1 < 17) { load_kv(kb + 1, (kb + 1) & 1); CP_COMMIT(); CP_WAIT(1); }
        else CP_WAIT(0);
        __syncthreads();

        const uint32_t sKb = smem_u32(sm + 16384 + (kb & 1) * 16384);
        const uint32_t sVb = sKb + 8192;

        float s[2][8][4];
#pragma unroll
        for (int mt = 0; mt < 2; ++mt)
#pragma unroll
            for (int nt = 0; nt < 8; ++nt)
#pragma unroll
                for (int j = 0; j < 4; ++j) s[mt][nt][j] = 0.f;

#pragma unroll
        for (int ks = 0; ks < 4; ++ks) {
            uint32_t qf[2][4];
            const int achk = ks * 2 + a_chk_l;
#pragma unroll
            for (int mt = 0; mt < 2; ++mt) {
                int row = wid * 32 + mt * 16 + a_row_l;
                ldsm4(qf[mt], sQb + row * 128 + ((achk ^ (row & 7)) << 4));
            }
            const int bchk = ks * 2 + b_chk_l;
#pragma unroll
            for (int np = 0; np < 4; ++np) {
                uint32_t kf[4];
                int row = np * 16 + b_row_l;
                ldsm4(kf, sKb + row * 128 + ((bchk ^ (row & 7)) << 4));
#pragma unroll
                for (int mt = 0; mt < 2; ++mt) {
                    mma_f16(s[mt][np * 2],     qf[mt], &kf[0]);
                    mma_f16(s[mt][np * 2 + 1], qf[mt], &kf[2]);
                }
            }
        }

        if (kb == 16) {
#pragma unroll
            for (int nt = 0; nt < 8; ++nt)
#pragma unroll
                for (int j = 0; j < 4; ++j) {
                    int tok = kb * 64 + nt * 8 + (lane & 3) * 2 + (j & 1);
                    if (tok > 1024) { s[0][nt][j] = -1e30f; s[1][nt][j] = -1e30f; }
                }
        }

#pragma unroll
        for (int mt = 0; mt < 2; ++mt) {
            float tm0 = -1e30f, tm1 = -1e30f;
#pragma unroll
            for (int nt = 0; nt < 8; ++nt) {
                tm0 = fmaxf(tm0, fmaxf(s[mt][nt][0], s[mt][nt][1]));
                tm1 = fmaxf(tm1, fmaxf(s[mt][nt][2], s[mt][nt][3]));
            }
            tm0 = fmaxf(tm0, __shfl_xor_sync(0xffffffffu, tm0, 1));
            tm0 = fmaxf(tm0, __shfl_xor_sync(0xffffffffu, tm0, 2));
            tm1 = fmaxf(tm1, __shfl_xor_sync(0xffffffffu, tm1, 1));
            tm1 = fmaxf(tm1, __shfl_xor_sync(0xffffffffu, tm1, 2));
            float mn0 = fmaxf(mr[mt][0], tm0), mn1 = fmaxf(mr[mt][1], tm1);
            float cr0 = ex2f(mr[mt][0] - mn0), cr1 = ex2f(mr[mt][1] - mn1);
            float rs0 = 0.f, rs1 = 0.f;
#pragma unroll
            for (int nt = 0; nt < 8; ++nt) {
                s[mt][nt][0] = ex2f(s[mt][nt][0] - mn0);
                s[mt][nt][1] = ex2f(s[mt][nt][1] - mn0);
                s[mt][nt][2] = ex2f(s[mt][nt][2] - mn1);
                s[mt][nt][3] = ex2f(s[mt][nt][3] - mn1);
                rs0 += s[mt][nt][0] + s[mt][nt][1];
                rs1 += s[mt][nt][2] + s[mt][nt][3];
            }
            rs0 += __shfl_xor_sync(0xffffffffu, rs0, 1);
            rs0 += __shfl_xor_sync(0xffffffffu, rs0, 2);
            rs1 += __shfl_xor_sync(0xffffffffu, rs1, 1);
            rs1 += __shfl_xor_sync(0xffffffffu, rs1, 2);
            lr[mt][0] = lr[mt][0] * cr0 + rs0;
            lr[mt][1] = lr[mt][1] * cr1 + rs1;
            mr[mt][0] = mn0; mr[mt][1] = mn1;
#pragma unroll
            for (int nt = 0; nt < 8; ++nt) {
                o[mt][nt][0] *= cr0; o[mt][nt][1] *= cr0;
                o[mt][nt][2] *= cr1; o[mt][nt][3] *= cr1;
            }
        }

#pragma unroll
        for (int k2 = 0; k2 < 4; ++k2) {
            uint32_t ph[2][4];
#pragma unroll
            for (int mt = 0; mt < 2; ++mt) {
                int t0 = 2 * k2, t1 = t0 + 1;
                ph[mt][0] = pack2h(s[mt][t0][0], s[mt][t0][1]);
                ph[mt][1] = pack2h(s[mt][t0][2], s[mt][t0][3]);
                ph[mt][2] = pack2h(s[mt][t1][0], s[mt][t1][1]);
                ph[mt][3] = pack2h(s[mt][t1][2], s[mt][t1][3]);
            }
#pragma unroll
            for (int ntp = 0; ntp < 4; ++ntp) {
                uint32_t vf[4];
                int row = k2 * 16 + (lane & 15);
                int chk = ntp * 2 + (lane >> 4);
                ldsm4_t(vf, sVb + row * 128 + ((chk ^ (row & 7)) << 4));
#pragma unroll
                for (int mt = 0; mt < 2; ++mt) {
                    mma_f16(o[mt][ntp * 2],     ph[mt], &vf[0]);
                    mma_f16(o[mt][ntp * 2 + 1], ph[mt], &vf[2]);
                }
            }
        }
        __syncthreads();
    }

#pragma unroll
    for (int mt = 0; mt < 2; ++mt) {
        float inv0 = 1.f / lr[mt][0], inv1 = 1.f / lr[mt][1];
        int tok0 = qt * 128 + wid * 32 + mt * 16 + (lane >> 2);
        int tok1 = tok0 + 8;
        int dbase = (lane & 3) * 2;
#pragma unroll
        for (int nt = 0; nt < 8; ++nt) {
            int d = nt * 8 + dbase;
            if (tok0 <= 1024) {
                size_t idx = (size_t)(tok0 * 8 + b) * 1024 + colb + d;
                *(uint32_t*)(Ctx + idx) = pack2h(o[mt][nt][0] * inv0, o[mt][nt][1] * inv0);
            }
            if (tok1 <= 1024) {
                size_t idx = (size_t)(tok1 * 8 + b) * 1024 + colb + d;
                *(uint32_t*)(Ctx + idx) = pack2h(o[mt][nt][2] * inv1, o[mt][nt][3] * inv1);
            }
        }
    }
}

// ---------------------------------------------------------------------------
// Launch
// ---------------------------------------------------------------------------
extern "C" void kernel_launch(void* const* d_in, const int* in_sizes, int n_in,
                              void* d_out, int out_size)
{
    const float* query = (const float*)d_in[0];
    const float* key   = (const float*)d_in[1];
    const float* value = (const float*)d_in[2];
    const float* W_in  = (const float*)d_in[3];
    const float* b_in  = (const float*)d_in[4];
    const float* W_out = (const float*)d_in[5];
    const float* b_out = (const float*)d_in[6];
    float* out = (float*)d_out;

    __half *qraw, *kraw, *vraw, *wi, *wo, *aq, *ak, *av, *ctx;
    cudaGetSymbolAddress((void**)&qraw, g_qraw);
    cudaGetSymbolAddress((void**)&kraw, g_kraw);
    cudaGetSymbolAddress((void**)&vraw, g_vraw);
    cudaGetSymbolAddress((void**)&wi, g_wi);
    cudaGetSymbolAddress((void**)&wo, g_wo);
    cudaGetSymbolAddress((void**)&aq, g_aq);
    cudaGetSymbolAddress((void**)&ak, g_ak);
    cudaGetSymbolAddress((void**)&av, g_av);
    cudaGetSymbolAddress((void**)&ctx, g_c);

    cudaFuncSetAttribute(tc_gemm_qkv, cudaFuncAttributeMaxDynamicSharedMemorySize, GK_SMEM);
    cudaFuncSetAttribute(tc_gemm_out, cudaFuncAttributeMaxDynamicSharedMemorySize, GK_SMEM);
    cudaFuncSetAttribute(attn_f16,    cudaFuncAttributeMaxDynamicSharedMemorySize, ATTN_SMEM);

    // fused input conversion + dummy-row fill
    split_all<<<(SPLIT_EXT + 1023) / 1024, 256>>>(
        (const float4*)query, (const float4*)key, (const float4*)value,
        (const float4*)W_in, (const float4*)W_out,
        (uint2*)qraw, (uint2*)kraw, (uint2*)vraw, (uint2*)wi, (uint2*)wo,
        (uint2*)aq, (uint2*)ak, (uint2*)av);

    // QKV projections (1-term fp16, 4-warp m64n64 tiles)
    tc_gemm_qkv<<<dim3(8, 64, 3), 128, GK_SMEM>>>(qraw, kraw, vraw, wi, b_in, aq, ak, av);

    // attention (fp16 mma.sync, 4 warps x m32)
    attn_f16<<<dim3(9, B_SZ * H_CNT), 128, ATTN_SMEM>>>(aq, ak, av, ctx);

    // out projection (1-term fp16)
    tc_gemm_out<<<dim3(8, 65), 128, GK_SMEM>>>(ctx, wo, b_out, out, NTOK);
}